// round 4
// baseline (speedup 1.0000x reference)
#include <cuda_runtime.h>
#include <cuda_bf16.h>
#include <math.h>

// Problem-fixed capacities
#define NMAX 50000
#define EMAX 800000

// ---------------- scratch (no allocation allowed) ----------------
__device__ int   g_is64;
__device__ int   g_deg[NMAX];
__device__ int   g_cursor[NMAX];
__device__ float g_dinv[NMAX];
__device__ int   g_rowptr[NMAX + 1];
__device__ int   g_col[EMAX];
__device__ float g_w[EMAX];
__device__ float g_bufA[NMAX * 128];
__device__ float g_bufB[NMAX * 128];

// Edge index accessor: handles int32 (JAX x64-disabled) and int64 layouts.
__device__ __forceinline__ int edge_at(const void* ei, long idx) {
    if (g_is64) return (int)((const long long*)ei)[idx];
    return ((const int*)ei)[idx];
}

// ---------------- dtype detection ----------------
__global__ void k_detect(const void* ei, int e) {
    if (threadIdx.x == 0 && blockIdx.x == 0) {
        const long long* p = (const long long*)ei;
        int ok = 1;
        int m = e < 2048 ? e : 2048;
        for (int i = 0; i < m; i++) {
            long long v = p[i];
            if (v < 0 || v >= NMAX) { ok = 0; break; }
        }
        g_is64 = ok;
    }
}

// ---------------- degree / dinv ----------------
__global__ void k_reset(int n) {
    int i = blockIdx.x * blockDim.x + threadIdx.x;
    if (i < n) g_deg[i] = 0;
}

__global__ void k_count(const void* __restrict__ ei, int e) {
    int i = blockIdx.x * blockDim.x + threadIdx.x;
    if (i < e) {
        int d = edge_at(ei, (long)e + i);  // dst row
        if (d >= 0 && d < NMAX) atomicAdd(&g_deg[d], 1);
    }
}

__global__ void k_dinv(int n) {
    int i = blockIdx.x * blockDim.x + threadIdx.x;
    if (i < n) g_dinv[i] = rsqrtf((float)(g_deg[i] + 1));  // +1 self loop
}

// ---------------- single-block exclusive scan (warp-scan based) ----------------
__global__ void k_scan(int n, int e_total) {
    __shared__ int warp_pref[32];
    __shared__ int s_carry;
    int tid = threadIdx.x, lane = tid & 31, wid = tid >> 5;
    if (tid == 0) s_carry = 0;
    __syncthreads();
    for (int base = 0; base < n; base += 1024) {
        int i = base + tid;
        int v = (i < n) ? g_deg[i] : 0;
        int incl = v;
        #pragma unroll
        for (int off = 1; off < 32; off <<= 1) {
            int t = __shfl_up_sync(0xffffffffu, incl, off);
            if (lane >= off) incl += t;
        }
        if (lane == 31) warp_pref[wid] = incl;
        __syncthreads();
        if (wid == 0) {
            int ws = warp_pref[lane];
            int wincl = ws;
            #pragma unroll
            for (int off = 1; off < 32; off <<= 1) {
                int t = __shfl_up_sync(0xffffffffu, wincl, off);
                if (lane >= off) wincl += t;
            }
            warp_pref[lane] = wincl - ws;  // exclusive warp prefix
        }
        __syncthreads();
        int excl = s_carry + warp_pref[wid] + incl - v;
        if (i < n) { g_rowptr[i] = excl; g_cursor[i] = excl; }
        __syncthreads();
        if (tid == 1023) s_carry = s_carry + warp_pref[31] + incl;
        __syncthreads();
    }
    if (threadIdx.x == 0) g_rowptr[n] = e_total;
}

// ---------------- CSR fill ----------------
__global__ void k_fill(const void* __restrict__ ei, int e) {
    int i = blockIdx.x * blockDim.x + threadIdx.x;
    if (i < e) {
        int s = edge_at(ei, i);
        int d = edge_at(ei, (long)e + i);
        if (s >= 0 && s < NMAX && d >= 0 && d < NMAX) {
            int pos = atomicAdd(&g_cursor[d], 1);
            if (pos >= 0 && pos < EMAX) {
                g_col[pos] = s;
                g_w[pos]   = g_dinv[s];
            }
        }
    }
}

// ---------------- tiled fp32 GEMM: C[M,ND] = A[M,KD] @ B[KD,ND] ----------------
template<int KD, int ND>
__global__ void __launch_bounds__(256) k_gemm(const float* __restrict__ A,
                                              const float* __restrict__ B,
                                              float* __restrict__ C, int M) {
    const int BM = 64, BN = 64, BK = 32;
    __shared__ float As[BK][BM];
    __shared__ float Bs[BK][BN];
    int bm = blockIdx.x * BM;
    int bn = blockIdx.y * BN;
    int tid = threadIdx.x;
    int tm = (tid >> 4) << 2;
    int tn = (tid & 15) << 2;
    float acc[4][4] = {};

    for (int k0 = 0; k0 < KD; k0 += BK) {
        #pragma unroll
        for (int i = tid; i < BM * BK; i += 256) {
            int m = i / BK, kk = i % BK;
            int gm = bm + m;
            As[kk][m] = (gm < M) ? A[(long)gm * KD + k0 + kk] : 0.f;
        }
        #pragma unroll
        for (int i = tid; i < BK * BN; i += 256) {
            int kk = i / BN, nn = i % BN;
            Bs[kk][nn] = B[(k0 + kk) * ND + bn + nn];
        }
        __syncthreads();
        #pragma unroll
        for (int kk = 0; kk < BK; kk++) {
            float a0 = As[kk][tm], a1 = As[kk][tm + 1], a2 = As[kk][tm + 2], a3 = As[kk][tm + 3];
            float b0 = Bs[kk][tn], b1 = Bs[kk][tn + 1], b2 = Bs[kk][tn + 2], b3 = Bs[kk][tn + 3];
            acc[0][0] += a0 * b0; acc[0][1] += a0 * b1; acc[0][2] += a0 * b2; acc[0][3] += a0 * b3;
            acc[1][0] += a1 * b0; acc[1][1] += a1 * b1; acc[1][2] += a1 * b2; acc[1][3] += a1 * b3;
            acc[2][0] += a2 * b0; acc[2][1] += a2 * b1; acc[2][2] += a2 * b2; acc[2][3] += a2 * b3;
            acc[3][0] += a3 * b0; acc[3][1] += a3 * b1; acc[3][2] += a3 * b2; acc[3][3] += a3 * b3;
        }
        __syncthreads();
    }
    #pragma unroll
    for (int i = 0; i < 4; i++) {
        int gm = bm + tm + i;
        if (gm < M) {
            #pragma unroll
            for (int j = 0; j < 4; j++)
                C[(long)gm * ND + bn + tn + j] = acc[i][j];
        }
    }
}

// ---------------- gather aggregation + bias + tanh (F=128) ----------------
__global__ void __launch_bounds__(256) k_agg128(const float* __restrict__ h,
                                                const float* __restrict__ bias,
                                                float* __restrict__ out, int n) {
    int node = blockIdx.x * 8 + (threadIdx.x >> 5);
    if (node >= n) return;
    int lane = threadIdx.x & 31;
    const float4* hv = (const float4*)h;
    float di = g_dinv[node];
    float4 a = __ldg(&hv[(long)node * 32 + lane]);
    float4 acc;
    acc.x = di * a.x; acc.y = di * a.y; acc.z = di * a.z; acc.w = di * a.w;
    int beg = g_rowptr[node], end = g_rowptr[node + 1];
    #pragma unroll 4
    for (int p = beg; p < end; p++) {
        int s = g_col[p];
        float ws = g_w[p];
        float4 v = __ldg(&hv[(long)s * 32 + lane]);
        acc.x += ws * v.x; acc.y += ws * v.y; acc.z += ws * v.z; acc.w += ws * v.w;
    }
    float4 b = __ldg(&((const float4*)bias)[lane]);
    float4 r;
    r.x = tanhf(di * acc.x + b.x);
    r.y = tanhf(di * acc.y + b.y);
    r.z = tanhf(di * acc.z + b.z);
    r.w = tanhf(di * acc.w + b.w);
    ((float4*)out)[(long)node * 32 + lane] = r;
}

// ---------------- gather aggregation + bias + tanh (F=64) ----------------
__global__ void __launch_bounds__(256) k_agg64(const float* __restrict__ h,
                                               const float* __restrict__ bias,
                                               float* __restrict__ out, int n) {
    int node = blockIdx.x * 8 + (threadIdx.x >> 5);
    if (node >= n) return;
    int lane = threadIdx.x & 31;
    const float2* hv = (const float2*)h;
    float di = g_dinv[node];
    float2 a = __ldg(&hv[(long)node * 32 + lane]);
    float2 acc;
    acc.x = di * a.x; acc.y = di * a.y;
    int beg = g_rowptr[node], end = g_rowptr[node + 1];
    #pragma unroll 4
    for (int p = beg; p < end; p++) {
        int s = g_col[p];
        float ws = g_w[p];
        float2 v = __ldg(&hv[(long)s * 32 + lane]);
        acc.x += ws * v.x; acc.y += ws * v.y;
    }
    float2 b = __ldg(&((const float2*)bias)[lane]);
    float2 r;
    r.x = tanhf(di * acc.x + b.x);
    r.y = tanhf(di * acc.y + b.y);
    ((float2*)out)[(long)node * 32 + lane] = r;
}

// ---------------- fused MLP head: tanh(h@Wf1+bf1)@Wf2+bf2 ----------------
__global__ void __launch_bounds__(256) k_mlp(const float* __restrict__ h,
                                             const float* __restrict__ Wf1,
                                             const float* __restrict__ bf1,
                                             const float* __restrict__ Wf2,
                                             const float* __restrict__ bf2,
                                             float* __restrict__ out, int n) {
    __shared__ float sW[64 * 32];
    __shared__ float sb1[32];
    __shared__ float sW2[32];
    __shared__ float sb2;
    for (int i = threadIdx.x; i < 64 * 32; i += blockDim.x) sW[i] = Wf1[i];
    if (threadIdx.x < 32) { sb1[threadIdx.x] = bf1[threadIdx.x]; sW2[threadIdx.x] = Wf2[threadIdx.x]; }
    if (threadIdx.x == 0) sb2 = bf2[0];
    __syncthreads();

    int node = blockIdx.x * 8 + (threadIdx.x >> 5);
    if (node >= n) return;
    int lane = threadIdx.x & 31;
    const float* row = h + (long)node * 64;
    float acc = sb1[lane];
    #pragma unroll
    for (int j = 0; j < 64; j++)
        acc += __ldg(&row[j]) * sW[j * 32 + lane];
    float t = tanhf(acc);
    float y = t * sW2[lane];
    #pragma unroll
    for (int off = 16; off; off >>= 1)
        y += __shfl_down_sync(0xffffffffu, y, off);
    if (lane == 0) out[node] = y + sb2;
}

// ---------------- launch ----------------
extern "C" void kernel_launch(void* const* d_in, const int* in_sizes, int n_in,
                              void* d_out, int out_size) {
    const float* x   = (const float*)d_in[0];
    const void*  ei  = d_in[1];
    const float* W1  = (const float*)d_in[2];
    const float* b1  = (const float*)d_in[3];
    const float* W2  = (const float*)d_in[4];
    const float* b2  = (const float*)d_in[5];
    const float* Wf1 = (const float*)d_in[6];
    const float* bf1 = (const float*)d_in[7];
    const float* Wf2 = (const float*)d_in[8];
    const float* bf2 = (const float*)d_in[9];
    float* out = (float*)d_out;

    int n = in_sizes[0] / 128;   // 50000
    int e = in_sizes[1] / 2;     // 800000

    float* bufA; cudaGetSymbolAddress((void**)&bufA, g_bufA);
    float* bufB; cudaGetSymbolAddress((void**)&bufB, g_bufB);

    int gn = (n + 255) / 256;
    int ge = (e + 255) / 256;
    int gw = (n + 7) / 8;        // warp-per-node kernels

    // CSR build
    k_detect<<<1, 32>>>(ei, e);
    k_reset<<<gn, 256>>>(n);
    k_count<<<ge, 256>>>(ei, e);
    k_dinv<<<gn, 256>>>(n);
    k_scan<<<1, 1024>>>(n, e);
    k_fill<<<ge, 256>>>(ei, e);

    // Layer 1: h1 = tanh(Agg(x@W1) + b1)   [n,128]
    {
        dim3 grid((n + 63) / 64, 2);
        k_gemm<128, 128><<<grid, 256>>>(x, W1, bufA, n);
    }
    k_agg128<<<gw, 256>>>(bufA, b1, bufB, n);

    // Layer 2: h2 = tanh(Agg(h1@W2) + b2)  [n,64]
    {
        dim3 grid((n + 63) / 64, 1);
        k_gemm<128, 64><<<grid, 256>>>(bufB, W2, bufA, n);
    }
    k_agg64<<<gw, 256>>>(bufA, b2, bufB, n);

    // Head: out = tanh(h2@Wf1+bf1)@Wf2+bf2  [n,1]
    k_mlp<<<gw, 256>>>(bufB, Wf1, bf1, Wf2, bf2, out, n);
}

// round 5
// speedup vs baseline: 1.3218x; 1.3218x over previous
#include <cuda_runtime.h>
#include <cuda_bf16.h>
#include <math.h>

// Problem-fixed capacities
#define NMAX 50000
#define EMAX 800000

// ---------------- scratch (no allocation allowed) ----------------
__device__ int   g_is64;
__device__ int   g_deg[NMAX];
__device__ int   g_cursor[NMAX];
__device__ float g_dinv[NMAX];
__device__ int   g_rowptr[NMAX + 1];
__device__ int   g_col[EMAX];
__device__ float g_w[EMAX];
__device__ __align__(256) float g_bufA[NMAX * 128];
__device__ __align__(256) float g_bufB[NMAX * 128];

// Edge index accessor: handles int32 (JAX x64-disabled) and int64 layouts.
__device__ __forceinline__ int edge_at(const void* ei, long idx) {
    if (g_is64) return (int)((const long long*)ei)[idx];
    return ((const int*)ei)[idx];
}

// ---------------- dtype detection (parallel) ----------------
__global__ void k_detect(const void* ei, int e) {
    const long long* p = (const long long*)ei;
    int m = e < 2048 ? e : 2048;
    int ok = 1;
    for (int i = threadIdx.x; i < m; i += blockDim.x) {
        long long v = p[i];
        if (v < 0 || v >= NMAX) ok = 0;
    }
    int all = __syncthreads_and(ok);
    if (threadIdx.x == 0) g_is64 = all;
}

// ---------------- degree / dinv ----------------
__global__ void k_reset(int n) {
    int i = blockIdx.x * blockDim.x + threadIdx.x;
    if (i < n) g_deg[i] = 0;
}

__global__ void k_count(const void* __restrict__ ei, int e) {
    int i = blockIdx.x * blockDim.x + threadIdx.x;
    if (i < e) {
        int d = edge_at(ei, (long)e + i);  // dst row
        if (d >= 0 && d < NMAX) atomicAdd(&g_deg[d], 1);
    }
}

__global__ void k_dinv(int n) {
    int i = blockIdx.x * blockDim.x + threadIdx.x;
    if (i < n) g_dinv[i] = rsqrtf((float)(g_deg[i] + 1));  // +1 self loop
}

// ---------------- single-block exclusive scan (warp-scan based) ----------------
__global__ void k_scan(int n, int e_total) {
    __shared__ int warp_pref[32];
    __shared__ int s_carry;
    int tid = threadIdx.x, lane = tid & 31, wid = tid >> 5;
    if (tid == 0) s_carry = 0;
    __syncthreads();
    for (int base = 0; base < n; base += 1024) {
        int i = base + tid;
        int v = (i < n) ? g_deg[i] : 0;
        int incl = v;
        #pragma unroll
        for (int off = 1; off < 32; off <<= 1) {
            int t = __shfl_up_sync(0xffffffffu, incl, off);
            if (lane >= off) incl += t;
        }
        if (lane == 31) warp_pref[wid] = incl;
        __syncthreads();
        if (wid == 0) {
            int ws = warp_pref[lane];
            int wincl = ws;
            #pragma unroll
            for (int off = 1; off < 32; off <<= 1) {
                int t = __shfl_up_sync(0xffffffffu, wincl, off);
                if (lane >= off) wincl += t;
            }
            warp_pref[lane] = wincl - ws;  // exclusive warp prefix
        }
        __syncthreads();
        int excl = s_carry + warp_pref[wid] + incl - v;
        if (i < n) { g_rowptr[i] = excl; g_cursor[i] = excl; }
        __syncthreads();
        if (tid == 1023) s_carry = s_carry + warp_pref[31] + incl;
        __syncthreads();
    }
    if (threadIdx.x == 0) g_rowptr[n] = e_total;
}

// ---------------- CSR fill ----------------
__global__ void k_fill(const void* __restrict__ ei, int e) {
    int i = blockIdx.x * blockDim.x + threadIdx.x;
    if (i < e) {
        int s = edge_at(ei, i);
        int d = edge_at(ei, (long)e + i);
        if (s >= 0 && s < NMAX && d >= 0 && d < NMAX) {
            int pos = atomicAdd(&g_cursor[d], 1);
            if (pos >= 0 && pos < EMAX) {
                g_col[pos] = s;
                g_w[pos]   = g_dinv[s];
            }
        }
    }
}

// ---------------- fp32 GEMM: C[M,ND] = A[M,KD] @ B[KD,ND] ----------------
// 128x64 CTA tile, BK=16, 8x4 per-thread, all-LDS.128 inner loop.
template<int KD, int ND>
__global__ void __launch_bounds__(256) k_gemm(const float* __restrict__ A,
                                              const float* __restrict__ B,
                                              float* __restrict__ C, int M) {
    const int BM = 128, BN = 64, BK = 16;
    __shared__ float As[BK][BM + 4];
    __shared__ float Bs[BK][BN];
    int bm = blockIdx.x * BM;
    int bn = blockIdx.y * BN;
    int tid = threadIdx.x;
    int tm = (tid >> 4) << 3;   // 0..120
    int tn = (tid & 15) << 2;   // 0..60
    float acc[8][4] = {};

    for (int k0 = 0; k0 < KD; k0 += BK) {
        // Load A tile: 512 float4s, transpose into As[kk][m]
        #pragma unroll
        for (int f = tid; f < 512; f += 256) {
            int ml = f >> 2, c = f & 3;
            int gm = bm + ml;
            float4 v = (gm < M) ? *(const float4*)&A[(long)gm * KD + k0 + 4 * c]
                                : make_float4(0.f, 0.f, 0.f, 0.f);
            As[4 * c + 0][ml] = v.x;
            As[4 * c + 1][ml] = v.y;
            As[4 * c + 2][ml] = v.z;
            As[4 * c + 3][ml] = v.w;
        }
        // Load B tile: 256 float4s, 1 per thread, no transpose
        {
            int kk = tid >> 4;
            int nn = (tid & 15) << 2;
            *(float4*)&Bs[kk][nn] = *(const float4*)&B[(long)(k0 + kk) * ND + bn + nn];
        }
        __syncthreads();
        #pragma unroll
        for (int kk = 0; kk < BK; kk++) {
            float4 a0 = *(const float4*)&As[kk][tm];
            float4 a1 = *(const float4*)&As[kk][tm + 4];
            float4 b  = *(const float4*)&Bs[kk][tn];
            acc[0][0] += a0.x * b.x; acc[0][1] += a0.x * b.y; acc[0][2] += a0.x * b.z; acc[0][3] += a0.x * b.w;
            acc[1][0] += a0.y * b.x; acc[1][1] += a0.y * b.y; acc[1][2] += a0.y * b.z; acc[1][3] += a0.y * b.w;
            acc[2][0] += a0.z * b.x; acc[2][1] += a0.z * b.y; acc[2][2] += a0.z * b.z; acc[2][3] += a0.z * b.w;
            acc[3][0] += a0.w * b.x; acc[3][1] += a0.w * b.y; acc[3][2] += a0.w * b.z; acc[3][3] += a0.w * b.w;
            acc[4][0] += a1.x * b.x; acc[4][1] += a1.x * b.y; acc[4][2] += a1.x * b.z; acc[4][3] += a1.x * b.w;
            acc[5][0] += a1.y * b.x; acc[5][1] += a1.y * b.y; acc[5][2] += a1.y * b.z; acc[5][3] += a1.y * b.w;
            acc[6][0] += a1.z * b.x; acc[6][1] += a1.z * b.y; acc[6][2] += a1.z * b.z; acc[6][3] += a1.z * b.w;
            acc[7][0] += a1.w * b.x; acc[7][1] += a1.w * b.y; acc[7][2] += a1.w * b.z; acc[7][3] += a1.w * b.w;
        }
        __syncthreads();
    }
    #pragma unroll
    for (int i = 0; i < 8; i++) {
        int gm = bm + tm + i;
        if (gm < M) {
            float4 v = make_float4(acc[i][0], acc[i][1], acc[i][2], acc[i][3]);
            *(float4*)&C[(long)gm * ND + bn + tn] = v;
        }
    }
}

// ---------------- gather aggregation + bias + tanh (F=128) ----------------
__global__ void __launch_bounds__(256) k_agg128(const float* __restrict__ h,
                                                const float* __restrict__ bias,
                                                float* __restrict__ out, int n) {
    int node = blockIdx.x * 8 + (threadIdx.x >> 5);
    if (node >= n) return;
    int lane = threadIdx.x & 31;
    const float4* hv = (const float4*)h;
    float di = g_dinv[node];
    float4 a = __ldg(&hv[(long)node * 32 + lane]);
    float4 acc;
    acc.x = di * a.x; acc.y = di * a.y; acc.z = di * a.z; acc.w = di * a.w;
    int beg = g_rowptr[node], end = g_rowptr[node + 1];
    #pragma unroll 4
    for (int p = beg; p < end; p++) {
        int s = g_col[p];
        float ws = g_w[p];
        float4 v = __ldg(&hv[(long)s * 32 + lane]);
        acc.x += ws * v.x; acc.y += ws * v.y; acc.z += ws * v.z; acc.w += ws * v.w;
    }
    float4 b = __ldg(&((const float4*)bias)[lane]);
    float4 r;
    r.x = tanhf(di * acc.x + b.x);
    r.y = tanhf(di * acc.y + b.y);
    r.z = tanhf(di * acc.z + b.z);
    r.w = tanhf(di * acc.w + b.w);
    ((float4*)out)[(long)node * 32 + lane] = r;
}

// ---------------- gather aggregation + bias + tanh (F=64) ----------------
__global__ void __launch_bounds__(256) k_agg64(const float* __restrict__ h,
                                               const float* __restrict__ bias,
                                               float* __restrict__ out, int n) {
    int node = blockIdx.x * 8 + (threadIdx.x >> 5);
    if (node >= n) return;
    int lane = threadIdx.x & 31;
    const float2* hv = (const float2*)h;
    float di = g_dinv[node];
    float2 a = __ldg(&hv[(long)node * 32 + lane]);
    float2 acc;
    acc.x = di * a.x; acc.y = di * a.y;
    int beg = g_rowptr[node], end = g_rowptr[node + 1];
    #pragma unroll 4
    for (int p = beg; p < end; p++) {
        int s = g_col[p];
        float ws = g_w[p];
        float2 v = __ldg(&hv[(long)s * 32 + lane]);
        acc.x += ws * v.x; acc.y += ws * v.y;
    }
    float2 b = __ldg(&((const float2*)bias)[lane]);
    float2 r;
    r.x = tanhf(di * acc.x + b.x);
    r.y = tanhf(di * acc.y + b.y);
    ((float2*)out)[(long)node * 32 + lane] = r;
}

// ---------------- fused MLP head: tanh(h@Wf1+bf1)@Wf2+bf2 ----------------
__global__ void __launch_bounds__(256) k_mlp(const float* __restrict__ h,
                                             const float* __restrict__ Wf1,
                                             const float* __restrict__ bf1,
                                             const float* __restrict__ Wf2,
                                             const float* __restrict__ bf2,
                                             float* __restrict__ out, int n) {
    __shared__ float sW[64 * 32];
    __shared__ float sb1[32];
    __shared__ float sW2[32];
    __shared__ float sb2;
    for (int i = threadIdx.x; i < 64 * 32; i += blockDim.x) sW[i] = Wf1[i];
    if (threadIdx.x < 32) { sb1[threadIdx.x] = bf1[threadIdx.x]; sW2[threadIdx.x] = Wf2[threadIdx.x]; }
    if (threadIdx.x == 0) sb2 = bf2[0];
    __syncthreads();

    int node = blockIdx.x * 8 + (threadIdx.x >> 5);
    if (node >= n) return;
    int lane = threadIdx.x & 31;
    const float* row = h + (long)node * 64;
    float acc = sb1[lane];
    #pragma unroll
    for (int j = 0; j < 64; j++)
        acc += __ldg(&row[j]) * sW[j * 32 + lane];
    float t = tanhf(acc);
    float y = t * sW2[lane];
    #pragma unroll
    for (int off = 16; off; off >>= 1)
        y += __shfl_down_sync(0xffffffffu, y, off);
    if (lane == 0) out[node] = y + sb2;
}

// ---------------- launch ----------------
extern "C" void kernel_launch(void* const* d_in, const int* in_sizes, int n_in,
                              void* d_out, int out_size) {
    const float* x   = (const float*)d_in[0];
    const void*  ei  = d_in[1];
    const float* W1  = (const float*)d_in[2];
    const float* b1  = (const float*)d_in[3];
    const float* W2  = (const float*)d_in[4];
    const float* b2  = (const float*)d_in[5];
    const float* Wf1 = (const float*)d_in[6];
    const float* bf1 = (const float*)d_in[7];
    const float* Wf2 = (const float*)d_in[8];
    const float* bf2 = (const float*)d_in[9];
    float* out = (float*)d_out;

    int n = in_sizes[0] / 128;   // 50000
    int e = in_sizes[1] / 2;     // 800000

    float* bufA; cudaGetSymbolAddress((void**)&bufA, g_bufA);
    float* bufB; cudaGetSymbolAddress((void**)&bufB, g_bufB);

    int gn = (n + 255) / 256;
    int ge = (e + 255) / 256;
    int gw = (n + 7) / 8;        // warp-per-node kernels

    // CSR build
    k_detect<<<1, 1024>>>(ei, e);
    k_reset<<<gn, 256>>>(n);
    k_count<<<ge, 256>>>(ei, e);
    k_dinv<<<gn, 256>>>(n);
    k_scan<<<1, 1024>>>(n, e);
    k_fill<<<ge, 256>>>(ei, e);

    // Layer 1: h1 = tanh(Agg(x@W1) + b1)   [n,128]
    {
        dim3 grid((n + 127) / 128, 2);
        k_gemm<128, 128><<<grid, 256>>>(x, W1, bufA, n);
    }
    k_agg128<<<gw, 256>>>(bufA, b1, bufB, n);

    // Layer 2: h2 = tanh(Agg(h1@W2) + b2)  [n,64]
    {
        dim3 grid((n + 127) / 128, 1);
        k_gemm<128, 64><<<grid, 256>>>(bufB, W2, bufA, n);
    }
    k_agg64<<<gw, 256>>>(bufA, b2, bufB, n);

    // Head: out = tanh(h2@Wf1+bf1)@Wf2+bf2  [n,1]
    k_mlp<<<gw, 256>>>(bufB, Wf1, bf1, Wf2, bf2, out, n);
}